// round 10
// baseline (speedup 1.0000x reference)
#include <cuda_runtime.h>

// FINAL — interactionModule_77936476554069
//
// Math: reference's zeroPotential makes force = ||dr|| * 0.0 == 0.0f for every
// edge (dr finite, normalize denominator clamped to >=1e-12, so no 0*inf/0*nan
// path). All 6.4M edge messages are exact zeros; segment_sum of zeros is zero.
// Therefore a = -GAMMA * v elementwise over N*D = 200000 floats, bitwise equal
// to the reference (rel_err 0.0 measured). The edge pipeline is elided.
//
// Kernel (measured best, dur 5.06-5.12us across two benches):
//   49 blocks x 512 threads = 25088 threads, one 256-bit ld.global.nc.v8 +
//   one 256-bit st.global.v8 each (n8 = 25000), single CTA wave.
// Session evidence: the v8 wavefront halving was the only material in-kernel
// win (-0.8us); grid-shape/MLP variants were neutral or regressed. Remaining
// ~5us is launch ramp + graph-replay overhead (harness-owned floor).

#define GAMMA 0.1f

__global__ void __launch_bounds__(512) scale_v_kernel(const float* __restrict__ v,
                                                      float* __restrict__ out,
                                                      int n8) {
    int i = blockIdx.x * 512 + threadIdx.x;
    if (i < n8) {
        const float* src = v + (size_t)i * 8;
        float* dst = out + (size_t)i * 8;
        float a0, a1, a2, a3, a4, a5, a6, a7;
        asm volatile(
            "ld.global.nc.v8.f32 {%0,%1,%2,%3,%4,%5,%6,%7}, [%8];"
            : "=f"(a0), "=f"(a1), "=f"(a2), "=f"(a3),
              "=f"(a4), "=f"(a5), "=f"(a6), "=f"(a7)
            : "l"(src));
        a0 = -GAMMA * a0; a1 = -GAMMA * a1; a2 = -GAMMA * a2; a3 = -GAMMA * a3;
        a4 = -GAMMA * a4; a5 = -GAMMA * a5; a6 = -GAMMA * a6; a7 = -GAMMA * a7;
        asm volatile(
            "st.global.v8.f32 [%0], {%1,%2,%3,%4,%5,%6,%7,%8};"
            :: "l"(dst),
               "f"(a0), "f"(a1), "f"(a2), "f"(a3),
               "f"(a4), "f"(a5), "f"(a6), "f"(a7)
            : "memory");
    }
}

// Tail safety for out_size % 8 != 0 (not hit for this shape: 200000 % 8 == 0).
__global__ void scale_v_tail_kernel(const float* __restrict__ v,
                                    float* __restrict__ out,
                                    int start, int n) {
    int i = start + blockIdx.x * blockDim.x + threadIdx.x;
    if (i < n) out[i] = -GAMMA * v[i];
}

extern "C" void kernel_launch(void* const* d_in, const int* in_sizes, int n_in,
                              void* d_out, int out_size) {
    // metadata order: x, v, src, dst
    const float* v = (const float*)d_in[1];
    float* out = (float*)d_out;

    int n = out_size;      // 200000
    int n8 = n / 8;        // 25000
    int tail = n - n8 * 8; // 0 for this shape

    const int TPB = 512;
    if (n8 > 0) {
        int blocks = (n8 + TPB - 1) / TPB;   // 49 -> single wave
        scale_v_kernel<<<blocks, TPB>>>(v, out, n8);
    }
    if (tail > 0) {
        int blocks = (tail + 255) / 256;
        scale_v_tail_kernel<<<blocks, 256>>>(v, out, n8 * 8, n);
    }
}

// round 12
// speedup vs baseline: 1.1677x; 1.1677x over previous
#include <cuda_runtime.h>

// FINAL — interactionModule_77936476554069  (R11 = byte-identical resubmit;
// previous round was a broker infra failure — this exact source has already
// passed 4 benches with rel_err 0.0).
//
// Math: reference's zeroPotential makes force = ||dr|| * 0.0 == 0.0f for every
// edge (dr finite, normalize denominator clamped to >=1e-12, so no 0*inf/0*nan
// path). All 6.4M edge messages are exact zeros; segment_sum of zeros is zero.
// Therefore a = -GAMMA * v elementwise over N*D = 200000 floats, bitwise equal
// to the reference. The edge pipeline is elided.
//
// Kernel (measured best): 49 blocks x 512 threads = 25088 threads, one 256-bit
// ld.global.nc.v8 + one 256-bit st.global.v8 each (n8 = 25000), single CTA wave.
//
// Session evidence: v8 wavefront halving was the only material in-kernel win
// (-0.8us). Identical-source dur measurements span 5.06-6.02us (run-to-run
// container noise ~ +/-0.5us), while ncu kernel time is stable at 4.3-4.5us —
// all remaining wall time is launch ramp + graph-replay + harness variance,
// which no .cu change can touch. Terminal.

#define GAMMA 0.1f

__global__ void __launch_bounds__(512) scale_v_kernel(const float* __restrict__ v,
                                                      float* __restrict__ out,
                                                      int n8) {
    int i = blockIdx.x * 512 + threadIdx.x;
    if (i < n8) {
        const float* src = v + (size_t)i * 8;
        float* dst = out + (size_t)i * 8;
        float a0, a1, a2, a3, a4, a5, a6, a7;
        asm volatile(
            "ld.global.nc.v8.f32 {%0,%1,%2,%3,%4,%5,%6,%7}, [%8];"
            : "=f"(a0), "=f"(a1), "=f"(a2), "=f"(a3),
              "=f"(a4), "=f"(a5), "=f"(a6), "=f"(a7)
            : "l"(src));
        a0 = -GAMMA * a0; a1 = -GAMMA * a1; a2 = -GAMMA * a2; a3 = -GAMMA * a3;
        a4 = -GAMMA * a4; a5 = -GAMMA * a5; a6 = -GAMMA * a6; a7 = -GAMMA * a7;
        asm volatile(
            "st.global.v8.f32 [%0], {%1,%2,%3,%4,%5,%6,%7,%8};"
            :: "l"(dst),
               "f"(a0), "f"(a1), "f"(a2), "f"(a3),
               "f"(a4), "f"(a5), "f"(a6), "f"(a7)
            : "memory");
    }
}

// Tail safety for out_size % 8 != 0 (not hit for this shape: 200000 % 8 == 0).
__global__ void scale_v_tail_kernel(const float* __restrict__ v,
                                    float* __restrict__ out,
                                    int start, int n) {
    int i = start + blockIdx.x * blockDim.x + threadIdx.x;
    if (i < n) out[i] = -GAMMA * v[i];
}

extern "C" void kernel_launch(void* const* d_in, const int* in_sizes, int n_in,
                              void* d_out, int out_size) {
    // metadata order: x, v, src, dst
    const float* v = (const float*)d_in[1];
    float* out = (float*)d_out;

    int n = out_size;      // 200000
    int n8 = n / 8;        // 25000
    int tail = n - n8 * 8; // 0 for this shape

    const int TPB = 512;
    if (n8 > 0) {
        int blocks = (n8 + TPB - 1) / TPB;   // 49 -> single wave
        scale_v_kernel<<<blocks, TPB>>>(v, out, n8);
    }
    if (tail > 0) {
        int blocks = (tail + 255) / 256;
        scale_v_tail_kernel<<<blocks, 256>>>(v, out, n8 * 8, n);
    }
}